// round 15
// baseline (speedup 1.0000x reference)
#include <cuda_runtime.h>
#include <cuda_fp16.h>
#include <math.h>
#include <cstdint>

// Problem constants
constexpr int B_ = 2, T_ = 2048, C_ = 2048, H_ = 16, HD_ = 128;
constexpr int M_ = B_ * T_;          // 4096
constexpr int NQKV = 3 * C_;         // 6144

// Scratch (allocation-free: __device__ globals), fp16 operands everywhere
__device__ __half g_Qh[(size_t)B_ * H_ * T_ * HD_];   // [B,H,T,HD], pre-scaled
__device__ __half g_Kh[(size_t)B_ * H_ * T_ * HD_];   // [B,H,T,HD]
__device__ __half g_Vh[(size_t)B_ * H_ * T_ * HD_];   // [B,H,T,HD] (t-major)
__device__ __half g_Yh[(size_t)M_ * C_];              // attention out [M,C]
__device__ __half g_xh[(size_t)M_ * C_];              // x fp16        [M,K]
__device__ __half g_Wqkvh[(size_t)C_ * NQKV];         // Wqkv fp16     [K,N] native
__device__ __half g_Wprojh[(size_t)C_ * C_];          // Wproj fp16    [K,N] native

// ---------------------------------------------------------------------------
// Helpers
// ---------------------------------------------------------------------------
__device__ __forceinline__ uint32_t smem_to_u32(const void* p) {
    uint32_t a;
    asm("{ .reg .u64 t; cvta.to.shared.u64 t, %1; cvt.u32.u64 %0, t; }"
        : "=r"(a) : "l"(p));
    return a;
}
__device__ __forceinline__ void cp_async16(uint32_t smem_addr, const void* gptr) {
    asm volatile("cp.async.cg.shared.global [%0], [%1], 16;"
                 :: "r"(smem_addr), "l"(gptr) : "memory");
}
#define CP_ASYNC_COMMIT() asm volatile("cp.async.commit_group;" ::: "memory")
#define CP_ASYNC_WAIT_ALL() asm volatile("cp.async.wait_group 0;" ::: "memory")
#define CP_ASYNC_WAIT_1()   asm volatile("cp.async.wait_group 1;" ::: "memory")
#define CP_ASYNC_WAIT_2()   asm volatile("cp.async.wait_group 2;" ::: "memory")

// m16n8k16 fp16 MMA, fp32 accumulate (sm_70+ baseline PTX)
__device__ __forceinline__ void mma_f16(float c[4],
                                        uint32_t a0, uint32_t a1, uint32_t a2, uint32_t a3,
                                        uint32_t b0, uint32_t b1) {
    asm volatile(
        "mma.sync.aligned.m16n8k16.row.col.f32.f16.f16.f32 "
        "{%0,%1,%2,%3}, {%4,%5,%6,%7}, {%8,%9}, {%0,%1,%2,%3};"
        : "+f"(c[0]), "+f"(c[1]), "+f"(c[2]), "+f"(c[3])
        : "r"(a0), "r"(a1), "r"(a2), "r"(a3), "r"(b0), "r"(b1));
}

__device__ __forceinline__ void ldsm_x4(uint32_t& r0, uint32_t& r1,
                                        uint32_t& r2, uint32_t& r3, uint32_t addr) {
    asm volatile("ldmatrix.sync.aligned.m8n8.x4.shared.b16 {%0,%1,%2,%3}, [%4];"
                 : "=r"(r0), "=r"(r1), "=r"(r2), "=r"(r3) : "r"(addr));
}
__device__ __forceinline__ void ldsm_x4_t(uint32_t& r0, uint32_t& r1,
                                          uint32_t& r2, uint32_t& r3, uint32_t addr) {
    asm volatile("ldmatrix.sync.aligned.m8n8.x4.trans.shared.b16 {%0,%1,%2,%3}, [%4];"
                 : "=r"(r0), "=r"(r1), "=r"(r2), "=r"(r3) : "r"(addr));
}

// ---------------------------------------------------------------------------
// Fused pre-pass: one launch converts x, W_qkv, W_proj fp32 -> fp16.
// ---------------------------------------------------------------------------
constexpr size_t NX  = (size_t)M_ * C_;        //  8,388,608
constexpr size_t NWQ = (size_t)C_ * NQKV;      // 12,582,912
constexpr size_t NWP = (size_t)C_ * C_;        //  4,194,304
constexpr size_t NTOT = NX + NWQ + NWP;        // 25,165,824 (mult of 8)

__global__ void __launch_bounds__(256)
cvt_all(const float* __restrict__ x, const float* __restrict__ wqkv,
        const float* __restrict__ wproj) {
    size_t i = ((size_t)blockIdx.x * 256 + threadIdx.x) * 8;
    const float* src;
    __half* dst;
    size_t off;
    if (i < NX)            { src = x;     dst = g_xh;     off = i; }
    else if (i < NX + NWQ) { src = wqkv;  dst = g_Wqkvh;  off = i - NX; }
    else                   { src = wproj; dst = g_Wprojh; off = i - NX - NWQ; }
    float4 v0 = *(const float4*)(src + off);
    float4 v1 = *(const float4*)(src + off + 4);
    __half2 h[4];
    h[0] = __floats2half2_rn(v0.x, v0.y);
    h[1] = __floats2half2_rn(v0.z, v0.w);
    h[2] = __floats2half2_rn(v1.x, v1.y);
    h[3] = __floats2half2_rn(v1.z, v1.w);
    *(uint4*)(dst + off) = *reinterpret_cast<uint4*>(h);
}

// ---------------------------------------------------------------------------
// PERSISTENT fp16 tensor GEMM: D[m][n] = sum_k A[m][k] * Bw[k][n].
// 128 threads (4 warps), BM=64, BN=128, BK=32, 4-stage cp.async ring.
// EXACT WAIT LEDGER: commit c loads stage for iter c-1; at iter j we need
// commit j+1 complete. Commits issued by iter j = min(3+j, NT).
//   j <= NT-3: wait_group 2  (min(3+j,NT)-2 >= j+1, exact)
//   j == NT-2: wait_group 1  (NT-1 complete)
//   j == NT-1: wait_group 0  (NT complete)
// Persistent tile loop, bn-major (concurrent CTAs share B -> L2 reuse).
// mode 0: out fp32 [m][n] = D + bias[n]
// mode 1: QKV scatter: Q (scaled) / K / V -> [B,H,T,HD] half (coalesced)
// ---------------------------------------------------------------------------
constexpr int AST = 40;    // A tile row stride (halves): 32 + 8 pad
constexpr int BST = 136;   // B tile row stride (halves): 128 + 8 pad
constexpr int A_STAGE = 64 * AST * 2;                  //  5120 B
constexpr int B_STAGE = 32 * BST * 2;                  //  8704 B
constexpr int GEMM_STAGE_BYTES = A_STAGE + B_STAGE;    // 13824
constexpr int GEMM_SMEM_BYTES  = 4 * GEMM_STAGE_BYTES; // 55296
constexpr float QSCALE = 0.08838834764831845f;         // 128^-0.5

__global__ void __launch_bounds__(128, 4)
gemm_h(const __half* __restrict__ A, const __half* __restrict__ Bw,
       const float* __restrict__ bias, float* __restrict__ out,
       int K, int ldB, int mode, int ldo, int nBm, int numTiles) {
    extern __shared__ __half smh[];
    const uint32_t sb = smem_to_u32(smh);
    const int tid = threadIdx.x;
    const int wid = tid >> 5, lane = tid & 31;
    const int wm = (wid >> 1) * 32;      // 0 / 32
    const int wn = (wid & 1) * 64;       // 0 / 64
    const int fr = lane >> 2, tq = lane & 3;

    // A ldmatrix (non-trans) per-lane offset (bytes)
    const uint32_t aoff =
        (uint32_t)(((wm + (lane & 7) + ((lane >> 3) & 1) * 8) * AST
                    + ((lane >> 4) & 1) * 8) * 2);
    // B trans-ldmatrix per-lane offset (halves; rows = k, cols = n)
    const uint32_t btoff =
        (uint32_t)(((lane & 7) + ((lane >> 3) & 1) * 8) * BST
                   + ((lane >> 4) & 1) * 8 + wn);

    // per-thread load-offset shapes (tile-independent)
    const int aU0r = tid >> 2,            aU0c = tid & 3;
    const int aU1r = (128 + tid) >> 2,    aU1c = tid & 3;
    const int bUr  = tid >> 4,            bUc  = tid & 15;
    const size_t bStride = (size_t)32 * ldB;

    #pragma unroll 1
    for (int tile = blockIdx.x; tile < numTiles; tile += gridDim.x) {
        const int bn = tile / nBm;
        const int bm = tile - bn * nBm;

        float acc[2][8][4];
        #pragma unroll
        for (int mi = 0; mi < 2; mi++)
            #pragma unroll
            for (int ni = 0; ni < 8; ni++)
                #pragma unroll
                for (int q = 0; q < 4; q++) acc[mi][ni][q] = 0.f;

        // per-tile base pointers + per-thread offsets
        uint32_t aS[2]; const __half* aG[2];
        {
            const __half* gA = A + (size_t)bm * 64 * K;
            aS[0] = (uint32_t)(aU0r * (AST * 2) + aU0c * 16);
            aG[0] = gA + (size_t)aU0r * K + aU0c * 8;
            aS[1] = (uint32_t)(aU1r * (AST * 2) + aU1c * 16);
            aG[1] = gA + (size_t)aU1r * K + aU1c * 8;
        }
        uint32_t bS[4]; const __half* bG[4];
        {
            const __half* gB = Bw + (size_t)bn * 128;
            #pragma unroll
            for (int i = 0; i < 4; i++) {
                int r = bUr + i * 8;
                bS[i] = (uint32_t)(A_STAGE + r * (BST * 2) + bUc * 16);
                bG[i] = gB + (size_t)r * ldB + bUc * 8;
            }
        }

        auto load_stage = [&](int s) {
            const uint32_t base = sb + (uint32_t)s * GEMM_STAGE_BYTES;
            #pragma unroll
            for (int i = 0; i < 2; i++) cp_async16(base + aS[i], aG[i]);
            #pragma unroll
            for (int i = 0; i < 4; i++) cp_async16(base + bS[i], bG[i]);
            #pragma unroll
            for (int i = 0; i < 2; i++) aG[i] += 32;
            #pragma unroll
            for (int i = 0; i < 4; i++) bG[i] += bStride;
        };

        load_stage(0); CP_ASYNC_COMMIT();
        load_stage(1); CP_ASYNC_COMMIT();
        load_stage(2); CP_ASYNC_COMMIT();

        const int NT = K / 32;
        #pragma unroll 1
        for (int j = 0; j < NT; j++) {
            if (j <= NT - 3)      CP_ASYNC_WAIT_2();
            else if (j == NT - 2) CP_ASYNC_WAIT_1();
            else                  CP_ASYNC_WAIT_ALL();
            __syncthreads();
            if (j + 3 < NT) {
                load_stage((j + 3) & 3);
                CP_ASYNC_COMMIT();
            }

            const uint32_t As_u = sb + (uint32_t)(j & 3) * GEMM_STAGE_BYTES;
            const uint32_t Bs_u = As_u + A_STAGE;

            #pragma unroll
            for (int ks = 0; ks < 2; ks++) {
                uint32_t a[2][4], bb[4][4];
                #pragma unroll
                for (int mi = 0; mi < 2; mi++)
                    ldsm_x4(a[mi][0], a[mi][1], a[mi][2], a[mi][3],
                            As_u + aoff + (uint32_t)((mi * 16 * AST + ks * 16) * 2));
                #pragma unroll
                for (int nj = 0; nj < 4; nj++)
                    ldsm_x4_t(bb[nj][0], bb[nj][1], bb[nj][2], bb[nj][3],
                              Bs_u + (uint32_t)((btoff + ks * 16 * BST
                                                 + nj * 16) * 2));
                #pragma unroll
                for (int mi = 0; mi < 2; mi++)
                    #pragma unroll
                    for (int ni = 0; ni < 8; ni++)
                        mma_f16(acc[mi][ni], a[mi][0], a[mi][1], a[mi][2], a[mi][3],
                                bb[ni >> 1][(ni & 1) * 2], bb[ni >> 1][(ni & 1) * 2 + 1]);
            }
        }
        __syncthreads();   // all warps done reading this tile's stages before
                           // the next tile's prologue overwrites them

        const int fc = tq * 2;

        if (mode == 1) {
            const int b  = bm >> 5;           // 32 m-tiles of 64 rows per b
            const int t0 = (bm & 31) * 64;
            const int n0g = bn * 128;
            const int s  = n0g >> 11;         // 0=Q 1=K 2=V
            const int h  = (n0g & 2047) >> 7;
            const float sc = (s == 0) ? QSCALE : 1.f;
            __half* base = ((s == 0) ? g_Qh : (s == 1) ? g_Kh : g_Vh)
                           + (size_t)(b * H_ + h) * T_ * HD_;
            #pragma unroll
            for (int mi = 0; mi < 2; mi++) {
                #pragma unroll
                for (int ni = 0; ni < 8; ni++) {
                    int t = t0 + wm + mi * 16 + fr;
                    int n = wn + ni * 8 + fc;
                    *(__half2*)(base + (size_t)t * HD_ + n) =
                        __floats2half2_rn(acc[mi][ni][0] * sc, acc[mi][ni][1] * sc);
                    *(__half2*)(base + (size_t)(t + 8) * HD_ + n) =
                        __floats2half2_rn(acc[mi][ni][2] * sc, acc[mi][ni][3] * sc);
                }
            }
        } else {
            #pragma unroll
            for (int mi = 0; mi < 2; mi++) {
                #pragma unroll
                for (int ni = 0; ni < 8; ni++) {
                    int m = bm * 64 + wm + mi * 16 + fr;
                    int n = bn * 128 + wn + ni * 8 + fc;
                    float b0 = bias[n], b1 = bias[n + 1];
                    *(float2*)(out + (size_t)m * ldo + n) =
                        make_float2(acc[mi][ni][0] + b0, acc[mi][ni][1] + b1);
                    *(float2*)(out + (size_t)(m + 8) * ldo + n) =
                        make_float2(acc[mi][ni][2] + b0, acc[mi][ni][3] + b1);
                }
            }
        }
    }
}

// ---------------------------------------------------------------------------
// fp16 tensor-core flash attention, causal. Br=128, Bc=64, HD=128, 8 warps.
// (R8/R9 proven version, unchanged)
// ---------------------------------------------------------------------------
constexpr int ASQ = 136;   // Q/K/V row stride, halves (272B: conflict-free)
constexpr int ATTN_SMEM_BYTES = (128 * ASQ + 4 * 64 * ASQ) * 2;   // 104448 B

__global__ void __launch_bounds__(256, 2)
attn_h() {
    extern __shared__ __half smh[];
    const uint32_t qs_b = smem_to_u32(smh);
    const uint32_t kv_b[2][2] = {
        { qs_b + 17408u * 2, qs_b + 26112u * 2 },   // Ks0, Vs0
        { qs_b + 34816u * 2, qs_b + 43520u * 2 }    // Ks1, Vs1
    };

    const int tid = threadIdx.x;
    const int w = tid >> 5, lane = tid & 31;
    const int fr = lane >> 2, tq = lane & 3;
    const int qi = (T_ / 128 - 1) - blockIdx.x;    // heavy blocks first
    const int h = blockIdx.y, b = blockIdx.z;
    const int q0 = qi * 128;

    const __half* Qg = g_Qh + (size_t)(b * H_ + h) * T_ * HD_;
    const __half* Kg = g_Kh + (size_t)(b * H_ + h) * T_ * HD_;
    const __half* Vg = g_Vh + (size_t)(b * H_ + h) * T_ * HD_;

    const uint32_t a_row = (lane & 7) + ((lane >> 3) & 1) * 8;
    const uint32_t a_col8 = ((lane >> 4) & 1) * 8;
    const uint32_t b_row = (lane & 7) + ((lane >> 4) & 1) * 8;
    const uint32_t b_col8 = ((lane >> 3) & 1) * 8;
    const uint32_t q_off = (uint32_t)(((w * 16 + a_row) * ASQ + a_col8) * 2);
    const uint32_t k_off = (uint32_t)((b_row * ASQ + b_col8) * 2);
    const uint32_t v_off = (uint32_t)((a_row * ASQ + a_col8) * 2);

    auto load_kv = [&](int buf, int k0) {
        #pragma unroll
        for (int i = 0; i < 4; i++) {
            int u = i * 256 + tid;
            int r = u >> 4, c = u & 15;
            cp_async16(kv_b[buf][0] + r * (ASQ * 2) + c * 16,
                       Kg + (size_t)(k0 + r) * HD_ + c * 8);
        }
        #pragma unroll
        for (int i = 0; i < 4; i++) {
            int u = i * 256 + tid;
            int r = u >> 4, c = u & 15;
            cp_async16(kv_b[buf][1] + r * (ASQ * 2) + c * 16,
                       Vg + (size_t)(k0 + r) * HD_ + c * 8);
        }
    };

    #pragma unroll
    for (int i = 0; i < 8; i++) {
        int u = i * 256 + tid;
        int r = u >> 4, c = u & 15;
        cp_async16(qs_b + r * (ASQ * 2) + c * 16,
                   Qg + (size_t)(q0 + r) * HD_ + c * 8);
    }
    load_kv(0, 0);
    CP_ASYNC_COMMIT();

    const int qrow0 = q0 + w * 16 + fr;
    const int qrow1 = qrow0 + 8;

    float m0 = -1e30f, m1 = -1e30f, l0 = 0.f, l1 = 0.f;
    float o[16][4];
    #pragma unroll
    for (int nf = 0; nf < 16; nf++)
        #pragma unroll
        for (int q = 0; q < 4; q++) o[nf][q] = 0.f;

    const int nkt = 2 * qi + 2;
    for (int kt = 0; kt < nkt; kt++) {
        const int k0 = kt * 64;
        const uint32_t ks_u = kv_b[kt & 1][0];
        const uint32_t vs_u = kv_b[kt & 1][1];

        CP_ASYNC_WAIT_ALL();
        __syncthreads();
        if (kt + 1 < nkt)
            load_kv((kt + 1) & 1, k0 + 64);
        CP_ASYNC_COMMIT();

        // ---- S = Q K^T ----
        float s[8][4];
        #pragma unroll
        for (int nf = 0; nf < 8; nf++)
            #pragma unroll
            for (int q = 0; q < 4; q++) s[nf][q] = 0.f;

        #pragma unroll
        for (int ks = 0; ks < 8; ks++) {
            uint32_t a0, a1, a2, a3, bb[4][4];
            ldsm_x4(a0, a1, a2, a3, qs_b + q_off + (uint32_t)(ks * 32));
            #pragma unroll
            for (int nj = 0; nj < 4; nj++)
                ldsm_x4(bb[nj][0], bb[nj][1], bb[nj][2], bb[nj][3],
                        ks_u + k_off + (uint32_t)((nj * 16 * ASQ) * 2 + ks * 32));
            #pragma unroll
            for (int nf = 0; nf < 8; nf++)
                mma_f16(s[nf], a0, a1, a2, a3,
                        bb[nf >> 1][(nf & 1) * 2], bb[nf >> 1][(nf & 1) * 2 + 1]);
        }

        // ---- causal mask ----
        if (kt >= 2 * qi) {
            #pragma unroll
            for (int nf = 0; nf < 8; nf++) {
                int col = k0 + nf * 8 + 2 * tq;
                if (col     > qrow0) s[nf][0] = -1e30f;
                if (col + 1 > qrow0) s[nf][1] = -1e30f;
                if (col     > qrow1) s[nf][2] = -1e30f;
                if (col + 1 > qrow1) s[nf][3] = -1e30f;
            }
        }

        // ---- online softmax ----
        float mx0 = -1e30f, mx1 = -1e30f;
        #pragma unroll
        for (int nf = 0; nf < 8; nf++) {
            mx0 = fmaxf(mx0, fmaxf(s[nf][0], s[nf][1]));
            mx1 = fmaxf(mx1, fmaxf(s[nf][2], s[nf][3]));
        }
        mx0 = fmaxf(mx0, __shfl_xor_sync(0xffffffffu, mx0, 1));
        mx0 = fmaxf(mx0, __shfl_xor_sync(0xffffffffu, mx0, 2));
        mx1 = fmaxf(mx1, __shfl_xor_sync(0xffffffffu, mx1, 1));
        mx1 = fmaxf(mx1, __shfl_xor_sync(0xffffffffu, mx1, 2));

        float mn0 = fmaxf(m0, mx0), mn1 = fmaxf(m1, mx1);
        float al0 = __expf(m0 - mn0), al1 = __expf(m1 - mn1);

        uint32_t pa[4][4];
        float ps0 = 0.f, ps1 = 0.f;
        #pragma unroll
        for (int nf = 0; nf < 8; nf++) {
            float p0 = __expf(s[nf][0] - mn0);
            float p1 = __expf(s[nf][1] - mn0);
            float p2 = __expf(s[nf][2] - mn1);
            float p3 = __expf(s[nf][3] - mn1);
            ps0 += p0 + p1; ps1 += p2 + p3;
            const int ks2 = nf >> 1, lo = (nf & 1) * 2;
            __half2 h01 = __floats2half2_rn(p0, p1);
            __half2 h23 = __floats2half2_rn(p2, p3);
            pa[ks2][lo]     = *reinterpret_cast<uint32_t*>(&h01);
            pa[ks2][lo + 1] = *reinterpret_cast<uint32_t*>(&h23);
        }
        ps0 += __shfl_xor_sync(0xffffffffu, ps0, 1);
        ps0 += __shfl_xor_sync(0xffffffffu, ps0, 2);
        ps1 += __shfl_xor_sync(0xffffffffu, ps1, 1);
        ps1 += __shfl_xor_sync(0xffffffffu, ps1, 2);
        l0 = l0 * al0 + ps0; m0 = mn0;
        l1 = l1 * al1 + ps1; m1 = mn1;

        #pragma unroll
        for (int nf = 0; nf < 16; nf++) {
            o[nf][0] *= al0; o[nf][1] *= al0;
            o[nf][2] *= al1; o[nf][3] *= al1;
        }

        // ---- O += P V : 8 d-tiles cover full HD=128 ----
        #pragma unroll
        for (int ks2 = 0; ks2 < 4; ks2++) {
            #pragma unroll
            for (int nj = 0; nj < 8; nj++) {
                uint32_t r0, r1, r2, r3;
                ldsm_x4_t(r0, r1, r2, r3,
                          vs_u + v_off +
                          (uint32_t)((ks2 * 16 * ASQ + nj * 16) * 2));
                mma_f16(o[nj * 2],     pa[ks2][0], pa[ks2][1], pa[ks2][2], pa[ks2][3], r0, r1);
                mma_f16(o[nj * 2 + 1], pa[ks2][0], pa[ks2][1], pa[ks2][2], pa[ks2][3], r2, r3);
            }
        }
    }

    // ---- epilogue ----
    const float inv0 = 1.f / l0, inv1 = 1.f / l1;
    __half* y0 = g_Yh + (size_t)(b * T_ + qrow0) * C_ + h * HD_;
    __half* y1 = g_Yh + (size_t)(b * T_ + qrow1) * C_ + h * HD_;
    #pragma unroll
    for (int nf = 0; nf < 16; nf++) {
        int c = nf * 8 + 2 * tq;
        *(__half2*)(y0 + c) = __floats2half2_rn(o[nf][0] * inv0, o[nf][1] * inv0);
        *(__half2*)(y1 + c) = __floats2half2_rn(o[nf][2] * inv1, o[nf][3] * inv1);
    }
}

// ---------------------------------------------------------------------------
// Launch. Inputs (metadata order): x, mask, W_qkv, W_proj, b_proj
// ---------------------------------------------------------------------------
extern "C" void kernel_launch(void* const* d_in, const int* in_sizes, int n_in,
                              void* d_out, int out_size) {
    const float* x     = (const float*)d_in[0];
    const float* Wqkv  = (const float*)d_in[2];
    const float* Wproj = (const float*)d_in[3];
    const float* bproj = (const float*)d_in[4];
    float* out = (float*)d_out;

    static int gemm_grid = 0;
    if (gemm_grid == 0) {
        cudaFuncSetAttribute(attn_h,
                             cudaFuncAttributeMaxDynamicSharedMemorySize,
                             ATTN_SMEM_BYTES);
        cudaFuncSetAttribute(gemm_h,
                             cudaFuncAttributeMaxDynamicSharedMemorySize,
                             GEMM_SMEM_BYTES);
        int dev = 0, sms = 148;
        cudaGetDevice(&dev);
        cudaDeviceGetAttribute(&sms, cudaDevAttrMultiProcessorCount, dev);
        gemm_grid = sms * 4;    // 4 CTAs/SM (smem+reg verified)
    }

    __half* xh;  cudaGetSymbolAddress((void**)&xh,  g_xh);
    __half* wq;  cudaGetSymbolAddress((void**)&wq,  g_Wqkvh);
    __half* wp;  cudaGetSymbolAddress((void**)&wp,  g_Wprojh);
    __half* yh;  cudaGetSymbolAddress((void**)&yh,  g_Yh);

    // Fused pre-pass: all fp32 -> fp16 conversions, one launch
    cvt_all<<<(int)(NTOT / 2048), 256>>>(x, Wqkv, Wproj);

    // QKV projection (persistent): tiles = (NQKV/128) * (M/64) = 3072
    {
        const int nBm = M_ / 64, nTiles = (NQKV / 128) * nBm;
        gemm_h<<<gemm_grid < nTiles ? gemm_grid : nTiles, 128, GEMM_SMEM_BYTES>>>(
            xh, wq, nullptr, nullptr, C_, NQKV, 1, 0, nBm, nTiles);
    }

    // Attention (fp16 tensor-core flash, causal)
    attn_h<<<dim3(T_ / 128, H_, B_), 256, ATTN_SMEM_BYTES>>>();

    // Output projection (persistent) + fp32 bias: tiles = 16 * 64 = 1024
    {
        const int nBm = M_ / 64, nTiles = (C_ / 128) * nBm;
        gemm_h<<<gemm_grid < nTiles ? gemm_grid : nTiles, 128, GEMM_SMEM_BYTES>>>(
            yh, wp, bproj, out, C_, C_, 0, C_, nBm, nTiles);
    }
}

// round 16
// speedup vs baseline: 1.0026x; 1.0026x over previous
#include <cuda_runtime.h>
#include <cuda_fp16.h>
#include <math.h>
#include <cstdint>

// Problem constants
constexpr int B_ = 2, T_ = 2048, C_ = 2048, H_ = 16, HD_ = 128;
constexpr int M_ = B_ * T_;          // 4096
constexpr int NQKV = 3 * C_;         // 6144

// Scratch (allocation-free: __device__ globals), fp16 operands everywhere
__device__ __half g_Qh[(size_t)B_ * H_ * T_ * HD_];   // [B,H,T,HD], pre-scaled
__device__ __half g_Kh[(size_t)B_ * H_ * T_ * HD_];   // [B,H,T,HD]
__device__ __half g_Vh[(size_t)B_ * H_ * T_ * HD_];   // [B,H,T,HD] (t-major)
__device__ __half g_Yh[(size_t)M_ * C_];              // attention out [M,C]
__device__ __half g_xh[(size_t)M_ * C_];              // x fp16        [M,K]
__device__ __half g_Wqkvh[(size_t)C_ * NQKV];         // Wqkv fp16     [K,N] native
__device__ __half g_Wprojh[(size_t)C_ * C_];          // Wproj fp16    [K,N] native

// ---------------------------------------------------------------------------
// Helpers
// ---------------------------------------------------------------------------
__device__ __forceinline__ uint32_t smem_to_u32(const void* p) {
    uint32_t a;
    asm("{ .reg .u64 t; cvta.to.shared.u64 t, %1; cvt.u32.u64 %0, t; }"
        : "=r"(a) : "l"(p));
    return a;
}
__device__ __forceinline__ void cp_async16(uint32_t smem_addr, const void* gptr) {
    asm volatile("cp.async.cg.shared.global [%0], [%1], 16;"
                 :: "r"(smem_addr), "l"(gptr) : "memory");
}
#define CP_ASYNC_COMMIT() asm volatile("cp.async.commit_group;" ::: "memory")
#define CP_ASYNC_WAIT_ALL() asm volatile("cp.async.wait_group 0;" ::: "memory")
#define CP_ASYNC_WAIT_1()   asm volatile("cp.async.wait_group 1;" ::: "memory")
#define CP_ASYNC_WAIT_2()   asm volatile("cp.async.wait_group 2;" ::: "memory")

// m16n8k16 fp16 MMA, fp32 accumulate (sm_70+ baseline PTX)
__device__ __forceinline__ void mma_f16(float c[4],
                                        uint32_t a0, uint32_t a1, uint32_t a2, uint32_t a3,
                                        uint32_t b0, uint32_t b1) {
    asm volatile(
        "mma.sync.aligned.m16n8k16.row.col.f32.f16.f16.f32 "
        "{%0,%1,%2,%3}, {%4,%5,%6,%7}, {%8,%9}, {%0,%1,%2,%3};"
        : "+f"(c[0]), "+f"(c[1]), "+f"(c[2]), "+f"(c[3])
        : "r"(a0), "r"(a1), "r"(a2), "r"(a3), "r"(b0), "r"(b1));
}

__device__ __forceinline__ void ldsm_x4(uint32_t& r0, uint32_t& r1,
                                        uint32_t& r2, uint32_t& r3, uint32_t addr) {
    asm volatile("ldmatrix.sync.aligned.m8n8.x4.shared.b16 {%0,%1,%2,%3}, [%4];"
                 : "=r"(r0), "=r"(r1), "=r"(r2), "=r"(r3) : "r"(addr));
}
__device__ __forceinline__ void ldsm_x4_t(uint32_t& r0, uint32_t& r1,
                                          uint32_t& r2, uint32_t& r3, uint32_t addr) {
    asm volatile("ldmatrix.sync.aligned.m8n8.x4.trans.shared.b16 {%0,%1,%2,%3}, [%4];"
                 : "=r"(r0), "=r"(r1), "=r"(r2), "=r"(r3) : "r"(addr));
}

// ---------------------------------------------------------------------------
// Fused pre-pass: one launch converts x, W_qkv, W_proj fp32 -> fp16.
// ---------------------------------------------------------------------------
constexpr size_t NX  = (size_t)M_ * C_;        //  8,388,608
constexpr size_t NWQ = (size_t)C_ * NQKV;      // 12,582,912
constexpr size_t NWP = (size_t)C_ * C_;        //  4,194,304
constexpr size_t NTOT = NX + NWQ + NWP;        // 25,165,824 (mult of 8)

__global__ void __launch_bounds__(256)
cvt_all(const float* __restrict__ x, const float* __restrict__ wqkv,
        const float* __restrict__ wproj) {
    size_t i = ((size_t)blockIdx.x * 256 + threadIdx.x) * 8;
    const float* src;
    __half* dst;
    size_t off;
    if (i < NX)            { src = x;     dst = g_xh;     off = i; }
    else if (i < NX + NWQ) { src = wqkv;  dst = g_Wqkvh;  off = i - NX; }
    else                   { src = wproj; dst = g_Wprojh; off = i - NX - NWQ; }
    float4 v0 = *(const float4*)(src + off);
    float4 v1 = *(const float4*)(src + off + 4);
    __half2 h[4];
    h[0] = __floats2half2_rn(v0.x, v0.y);
    h[1] = __floats2half2_rn(v0.z, v0.w);
    h[2] = __floats2half2_rn(v1.x, v1.y);
    h[3] = __floats2half2_rn(v1.z, v1.w);
    *(uint4*)(dst + off) = *reinterpret_cast<uint4*>(h);
}

// ---------------------------------------------------------------------------
// fp16 tensor GEMM: D[m][n] = sum_k A[m][k] * Bw[k][n], fp32 accumulate.
// 128 threads (4 warps), BM=64, BN=128, BK=32, 4-stage cp.async ring,
// strength-reduced addressing. Non-persistent (grid = tiles; HW work-steal
// balances waves). EXACT WAIT LEDGER: commit c loads stage for iter c-1;
// at iter j we need commit j+1 complete. Commits issued by iter j =
// min(3+j, NT):
//   j <= NT-3: wait_group 2   (exact)
//   j == NT-2: wait_group 1
//   j == NT-1: wait_group 0
// mode 0: out fp32 [m][n] = D + bias[n]
// mode 1: QKV scatter: Q (scaled) / K / V -> [B,H,T,HD] half (coalesced)
// ---------------------------------------------------------------------------
constexpr int AST = 40;    // A tile row stride (halves): 32 + 8 pad
constexpr int BST = 136;   // B tile row stride (halves): 128 + 8 pad
constexpr int A_STAGE = 64 * AST * 2;                  //  5120 B
constexpr int B_STAGE = 32 * BST * 2;                  //  8704 B
constexpr int GEMM_STAGE_BYTES = A_STAGE + B_STAGE;    // 13824
constexpr int GEMM_SMEM_BYTES  = 4 * GEMM_STAGE_BYTES; // 55296
constexpr float QSCALE = 0.08838834764831845f;         // 128^-0.5

__global__ void __launch_bounds__(128, 4)
gemm_h(const __half* __restrict__ A, const __half* __restrict__ Bw,
       const float* __restrict__ bias, float* __restrict__ out,
       int K, int ldB, int mode, int ldo) {
    extern __shared__ __half smh[];
    const uint32_t sb = smem_to_u32(smh);
    const int tid = threadIdx.x;
    const int wid = tid >> 5, lane = tid & 31;
    const int bm = blockIdx.y, bn = blockIdx.x;
    const int wm = (wid >> 1) * 32;      // 0 / 32
    const int wn = (wid & 1) * 64;       // 0 / 64
    const int fr = lane >> 2, tq = lane & 3;

    // A ldmatrix (non-trans) per-lane offset (bytes)
    const uint32_t aoff =
        (uint32_t)(((wm + (lane & 7) + ((lane >> 3) & 1) * 8) * AST
                    + ((lane >> 4) & 1) * 8) * 2);
    // B trans-ldmatrix per-lane offset (halves; rows = k, cols = n)
    const uint32_t btoff =
        (uint32_t)(((lane & 7) + ((lane >> 3) & 1) * 8) * BST
                   + ((lane >> 4) & 1) * 8 + wn);

    float acc[2][8][4];
    #pragma unroll
    for (int mi = 0; mi < 2; mi++)
        #pragma unroll
        for (int ni = 0; ni < 8; ni++)
            #pragma unroll
            for (int q = 0; q < 4; q++) acc[mi][ni][q] = 0.f;

    // ---- precomputed per-thread load offsets (ONCE) ----
    uint32_t aS[2]; const __half* aG[2];
    {
        const __half* gA = A + (size_t)bm * 64 * K;
        const int r0 = tid >> 2, c0 = tid & 3;
        const int r1 = (128 + tid) >> 2;
        aS[0] = (uint32_t)(r0 * (AST * 2) + c0 * 16);
        aG[0] = gA + (size_t)r0 * K + c0 * 8;
        aS[1] = (uint32_t)(r1 * (AST * 2) + c0 * 16);
        aG[1] = gA + (size_t)r1 * K + c0 * 8;
    }
    uint32_t bS[4]; const __half* bG[4];
    {
        const __half* gB = Bw + (size_t)bn * 128;
        const int r = tid >> 4, c = tid & 15;
        #pragma unroll
        for (int i = 0; i < 4; i++) {
            int rr = r + i * 8;
            bS[i] = (uint32_t)(A_STAGE + rr * (BST * 2) + c * 16);
            bG[i] = gB + (size_t)rr * ldB + c * 8;
        }
    }
    const size_t bStride = (size_t)32 * ldB;

    auto load_stage = [&](int s) {
        const uint32_t base = sb + (uint32_t)s * GEMM_STAGE_BYTES;
        #pragma unroll
        for (int i = 0; i < 2; i++) cp_async16(base + aS[i], aG[i]);
        #pragma unroll
        for (int i = 0; i < 4; i++) cp_async16(base + bS[i], bG[i]);
        #pragma unroll
        for (int i = 0; i < 2; i++) aG[i] += 32;
        #pragma unroll
        for (int i = 0; i < 4; i++) bG[i] += bStride;
    };

    load_stage(0); CP_ASYNC_COMMIT();
    load_stage(1); CP_ASYNC_COMMIT();
    load_stage(2); CP_ASYNC_COMMIT();

    const int NT = K / 32;
    #pragma unroll 1
    for (int j = 0; j < NT; j++) {
        if (j <= NT - 3)      CP_ASYNC_WAIT_2();
        else if (j == NT - 2) CP_ASYNC_WAIT_1();
        else                  CP_ASYNC_WAIT_ALL();
        __syncthreads();
        if (j + 3 < NT) {
            load_stage((j + 3) & 3);
            CP_ASYNC_COMMIT();
        }

        const uint32_t As_u = sb + (uint32_t)(j & 3) * GEMM_STAGE_BYTES;
        const uint32_t Bs_u = As_u + A_STAGE;

        #pragma unroll
        for (int ks = 0; ks < 2; ks++) {
            uint32_t a[2][4], bb[4][4];
            #pragma unroll
            for (int mi = 0; mi < 2; mi++)
                ldsm_x4(a[mi][0], a[mi][1], a[mi][2], a[mi][3],
                        As_u + aoff + (uint32_t)((mi * 16 * AST + ks * 16) * 2));
            #pragma unroll
            for (int nj = 0; nj < 4; nj++)
                ldsm_x4_t(bb[nj][0], bb[nj][1], bb[nj][2], bb[nj][3],
                          Bs_u + (uint32_t)((btoff + ks * 16 * BST
                                             + nj * 16) * 2));
            #pragma unroll
            for (int mi = 0; mi < 2; mi++)
                #pragma unroll
                for (int ni = 0; ni < 8; ni++)
                    mma_f16(acc[mi][ni], a[mi][0], a[mi][1], a[mi][2], a[mi][3],
                            bb[ni >> 1][(ni & 1) * 2], bb[ni >> 1][(ni & 1) * 2 + 1]);
        }
    }

    const int fc = tq * 2;

    if (mode == 1) {
        const int b  = bm >> 5;               // 32 m-tiles of 64 rows per b
        const int t0 = (bm & 31) * 64;
        const int n0g = bn * 128;
        const int s  = n0g >> 11;             // 0=Q 1=K 2=V
        const int h  = (n0g & 2047) >> 7;
        const float sc = (s == 0) ? QSCALE : 1.f;
        __half* base = ((s == 0) ? g_Qh : (s == 1) ? g_Kh : g_Vh)
                       + (size_t)(b * H_ + h) * T_ * HD_;
        #pragma unroll
        for (int mi = 0; mi < 2; mi++) {
            #pragma unroll
            for (int ni = 0; ni < 8; ni++) {
                int t = t0 + wm + mi * 16 + fr;
                int n = wn + ni * 8 + fc;
                *(__half2*)(base + (size_t)t * HD_ + n) =
                    __floats2half2_rn(acc[mi][ni][0] * sc, acc[mi][ni][1] * sc);
                *(__half2*)(base + (size_t)(t + 8) * HD_ + n) =
                    __floats2half2_rn(acc[mi][ni][2] * sc, acc[mi][ni][3] * sc);
            }
        }
    } else {
        #pragma unroll
        for (int mi = 0; mi < 2; mi++) {
            #pragma unroll
            for (int ni = 0; ni < 8; ni++) {
                int m = bm * 64 + wm + mi * 16 + fr;
                int n = bn * 128 + wn + ni * 8 + fc;
                float b0 = bias[n], b1 = bias[n + 1];
                *(float2*)(out + (size_t)m * ldo + n) =
                    make_float2(acc[mi][ni][0] + b0, acc[mi][ni][1] + b1);
                *(float2*)(out + (size_t)(m + 8) * ldo + n) =
                    make_float2(acc[mi][ni][2] + b0, acc[mi][ni][3] + b1);
            }
        }
    }
}

// ---------------------------------------------------------------------------
// fp16 tensor-core flash attention, causal. Br=128, Bc=64, HD=128, 8 warps.
// (R8/R9 proven version, unchanged)
// ---------------------------------------------------------------------------
constexpr int ASQ = 136;   // Q/K/V row stride, halves (272B: conflict-free)
constexpr int ATTN_SMEM_BYTES = (128 * ASQ + 4 * 64 * ASQ) * 2;   // 104448 B

__global__ void __launch_bounds__(256, 2)
attn_h() {
    extern __shared__ __half smh[];
    const uint32_t qs_b = smem_to_u32(smh);
    const uint32_t kv_b[2][2] = {
        { qs_b + 17408u * 2, qs_b + 26112u * 2 },   // Ks0, Vs0
        { qs_b + 34816u * 2, qs_b + 43520u * 2 }    // Ks1, Vs1
    };

    const int tid = threadIdx.x;
    const int w = tid >> 5, lane = tid & 31;
    const int fr = lane >> 2, tq = lane & 3;
    const int qi = (T_ / 128 - 1) - blockIdx.x;    // heavy blocks first
    const int h = blockIdx.y, b = blockIdx.z;
    const int q0 = qi * 128;

    const __half* Qg = g_Qh + (size_t)(b * H_ + h) * T_ * HD_;
    const __half* Kg = g_Kh + (size_t)(b * H_ + h) * T_ * HD_;
    const __half* Vg = g_Vh + (size_t)(b * H_ + h) * T_ * HD_;

    const uint32_t a_row = (lane & 7) + ((lane >> 3) & 1) * 8;
    const uint32_t a_col8 = ((lane >> 4) & 1) * 8;
    const uint32_t b_row = (lane & 7) + ((lane >> 4) & 1) * 8;
    const uint32_t b_col8 = ((lane >> 3) & 1) * 8;
    const uint32_t q_off = (uint32_t)(((w * 16 + a_row) * ASQ + a_col8) * 2);
    const uint32_t k_off = (uint32_t)((b_row * ASQ + b_col8) * 2);
    const uint32_t v_off = (uint32_t)((a_row * ASQ + a_col8) * 2);

    auto load_kv = [&](int buf, int k0) {
        #pragma unroll
        for (int i = 0; i < 4; i++) {
            int u = i * 256 + tid;
            int r = u >> 4, c = u & 15;
            cp_async16(kv_b[buf][0] + r * (ASQ * 2) + c * 16,
                       Kg + (size_t)(k0 + r) * HD_ + c * 8);
        }
        #pragma unroll
        for (int i = 0; i < 4; i++) {
            int u = i * 256 + tid;
            int r = u >> 4, c = u & 15;
            cp_async16(kv_b[buf][1] + r * (ASQ * 2) + c * 16,
                       Vg + (size_t)(k0 + r) * HD_ + c * 8);
        }
    };

    #pragma unroll
    for (int i = 0; i < 8; i++) {
        int u = i * 256 + tid;
        int r = u >> 4, c = u & 15;
        cp_async16(qs_b + r * (ASQ * 2) + c * 16,
                   Qg + (size_t)(q0 + r) * HD_ + c * 8);
    }
    load_kv(0, 0);
    CP_ASYNC_COMMIT();

    const int qrow0 = q0 + w * 16 + fr;
    const int qrow1 = qrow0 + 8;

    float m0 = -1e30f, m1 = -1e30f, l0 = 0.f, l1 = 0.f;
    float o[16][4];
    #pragma unroll
    for (int nf = 0; nf < 16; nf++)
        #pragma unroll
        for (int q = 0; q < 4; q++) o[nf][q] = 0.f;

    const int nkt = 2 * qi + 2;
    for (int kt = 0; kt < nkt; kt++) {
        const int k0 = kt * 64;
        const uint32_t ks_u = kv_b[kt & 1][0];
        const uint32_t vs_u = kv_b[kt & 1][1];

        CP_ASYNC_WAIT_ALL();
        __syncthreads();
        if (kt + 1 < nkt)
            load_kv((kt + 1) & 1, k0 + 64);
        CP_ASYNC_COMMIT();

        // ---- S = Q K^T ----
        float s[8][4];
        #pragma unroll
        for (int nf = 0; nf < 8; nf++)
            #pragma unroll
            for (int q = 0; q < 4; q++) s[nf][q] = 0.f;

        #pragma unroll
        for (int ks = 0; ks < 8; ks++) {
            uint32_t a0, a1, a2, a3, bb[4][4];
            ldsm_x4(a0, a1, a2, a3, qs_b + q_off + (uint32_t)(ks * 32));
            #pragma unroll
            for (int nj = 0; nj < 4; nj++)
                ldsm_x4(bb[nj][0], bb[nj][1], bb[nj][2], bb[nj][3],
                        ks_u + k_off + (uint32_t)((nj * 16 * ASQ) * 2 + ks * 32));
            #pragma unroll
            for (int nf = 0; nf < 8; nf++)
                mma_f16(s[nf], a0, a1, a2, a3,
                        bb[nf >> 1][(nf & 1) * 2], bb[nf >> 1][(nf & 1) * 2 + 1]);
        }

        // ---- causal mask ----
        if (kt >= 2 * qi) {
            #pragma unroll
            for (int nf = 0; nf < 8; nf++) {
                int col = k0 + nf * 8 + 2 * tq;
                if (col     > qrow0) s[nf][0] = -1e30f;
                if (col + 1 > qrow0) s[nf][1] = -1e30f;
                if (col     > qrow1) s[nf][2] = -1e30f;
                if (col + 1 > qrow1) s[nf][3] = -1e30f;
            }
        }

        // ---- online softmax ----
        float mx0 = -1e30f, mx1 = -1e30f;
        #pragma unroll
        for (int nf = 0; nf < 8; nf++) {
            mx0 = fmaxf(mx0, fmaxf(s[nf][0], s[nf][1]));
            mx1 = fmaxf(mx1, fmaxf(s[nf][2], s[nf][3]));
        }
        mx0 = fmaxf(mx0, __shfl_xor_sync(0xffffffffu, mx0, 1));
        mx0 = fmaxf(mx0, __shfl_xor_sync(0xffffffffu, mx0, 2));
        mx1 = fmaxf(mx1, __shfl_xor_sync(0xffffffffu, mx1, 1));
        mx1 = fmaxf(mx1, __shfl_xor_sync(0xffffffffu, mx1, 2));

        float mn0 = fmaxf(m0, mx0), mn1 = fmaxf(m1, mx1);
        float al0 = __expf(m0 - mn0), al1 = __expf(m1 - mn1);

        uint32_t pa[4][4];
        float ps0 = 0.f, ps1 = 0.f;
        #pragma unroll
        for (int nf = 0; nf < 8; nf++) {
            float p0 = __expf(s[nf][0] - mn0);
            float p1 = __expf(s[nf][1] - mn0);
            float p2 = __expf(s[nf][2] - mn1);
            float p3 = __expf(s[nf][3] - mn1);
            ps0 += p0 + p1; ps1 += p2 + p3;
            const int ks2 = nf >> 1, lo = (nf & 1) * 2;
            __half2 h01 = __floats2half2_rn(p0, p1);
            __half2 h23 = __floats2half2_rn(p2, p3);
            pa[ks2][lo]     = *reinterpret_cast<uint32_t*>(&h01);
            pa[ks2][lo + 1] = *reinterpret_cast<uint32_t*>(&h23);
        }
        ps0 += __shfl_xor_sync(0xffffffffu, ps0, 1);
        ps0 += __shfl_xor_sync(0xffffffffu, ps0, 2);
        ps1 += __shfl_xor_sync(0xffffffffu, ps1, 1);
        ps1 += __shfl_xor_sync(0xffffffffu, ps1, 2);
        l0 = l0 * al0 + ps0; m0 = mn0;
        l1 = l1 * al1 + ps1; m1 = mn1;

        #pragma unroll
        for (int nf = 0; nf < 16; nf++) {
            o[nf][0] *= al0; o[nf][1] *= al0;
            o[nf][2] *= al1; o[nf][3] *= al1;
        }

        // ---- O += P V : 8 d-tiles cover full HD=128 ----
        #pragma unroll
        for (int ks2 = 0; ks2 < 4; ks2++) {
            #pragma unroll
            for (int nj = 0; nj < 8; nj++) {
                uint32_t r0, r1, r2, r3;
                ldsm_x4_t(r0, r1, r2, r3,
                          vs_u + v_off +
                          (uint32_t)((ks2 * 16 * ASQ + nj * 16) * 2));
                mma_f16(o[nj * 2],     pa[ks2][0], pa[ks2][1], pa[ks2][2], pa[ks2][3], r0, r1);
                mma_f16(o[nj * 2 + 1], pa[ks2][0], pa[ks2][1], pa[ks2][2], pa[ks2][3], r2, r3);
            }
        }
    }

    // ---- epilogue ----
    const float inv0 = 1.f / l0, inv1 = 1.f / l1;
    __half* y0 = g_Yh + (size_t)(b * T_ + qrow0) * C_ + h * HD_;
    __half* y1 = g_Yh + (size_t)(b * T_ + qrow1) * C_ + h * HD_;
    #pragma unroll
    for (int nf = 0; nf < 16; nf++) {
        int c = nf * 8 + 2 * tq;
        *(__half2*)(y0 + c) = __floats2half2_rn(o[nf][0] * inv0, o[nf][1] * inv0);
        *(__half2*)(y1 + c) = __floats2half2_rn(o[nf][2] * inv1, o[nf][3] * inv1);
    }
}

// ---------------------------------------------------------------------------
// Launch. Inputs (metadata order): x, mask, W_qkv, W_proj, b_proj
// ---------------------------------------------------------------------------
extern "C" void kernel_launch(void* const* d_in, const int* in_sizes, int n_in,
                              void* d_out, int out_size) {
    const float* x     = (const float*)d_in[0];
    const float* Wqkv  = (const float*)d_in[2];
    const float* Wproj = (const float*)d_in[3];
    const float* bproj = (const float*)d_in[4];
    float* out = (float*)d_out;

    static bool attr_set = false;
    if (!attr_set) {
        cudaFuncSetAttribute(attn_h,
                             cudaFuncAttributeMaxDynamicSharedMemorySize,
                             ATTN_SMEM_BYTES);
        cudaFuncSetAttribute(gemm_h,
                             cudaFuncAttributeMaxDynamicSharedMemorySize,
                             GEMM_SMEM_BYTES);
        attr_set = true;
    }

    __half* xh;  cudaGetSymbolAddress((void**)&xh,  g_xh);
    __half* wq;  cudaGetSymbolAddress((void**)&wq,  g_Wqkvh);
    __half* wp;  cudaGetSymbolAddress((void**)&wp,  g_Wprojh);
    __half* yh;  cudaGetSymbolAddress((void**)&yh,  g_Yh);

    // Fused pre-pass: all fp32 -> fp16 conversions, one launch
    cvt_all<<<(int)(NTOT / 2048), 256>>>(x, Wqkv, Wproj);

    // QKV projection (fp16 tensor cores), B native [K,N]; scatter Q/K/V
    gemm_h<<<dim3(NQKV / 128, M_ / 64), 128, GEMM_SMEM_BYTES>>>(
        xh, wq, nullptr, nullptr, C_, NQKV, 1, 0);

    // Attention (fp16 tensor-core flash, causal)
    attn_h<<<dim3(T_ / 128, H_, B_), 256, ATTN_SMEM_BYTES>>>();

    // Output projection (fp16 tensor cores) + fp32 bias
    gemm_h<<<dim3(C_ / 128, M_ / 64), 128, GEMM_SMEM_BYTES>>>(
        yh, wp, bproj, out, C_, C_, 0, C_);
}

// round 17
// speedup vs baseline: 1.0290x; 1.0263x over previous
#include <cuda_runtime.h>
#include <cuda_fp16.h>
#include <math.h>
#include <cstdint>

// Problem constants
constexpr int B_ = 2, T_ = 2048, C_ = 2048, H_ = 16, HD_ = 128;
constexpr int M_ = B_ * T_;          // 4096
constexpr int NQKV = 3 * C_;         // 6144

// Scratch (allocation-free: __device__ globals), fp16 operands everywhere
__device__ __half g_Qh[(size_t)B_ * H_ * T_ * HD_];   // [B,H,T,HD], pre-scaled
__device__ __half g_Kh[(size_t)B_ * H_ * T_ * HD_];   // [B,H,T,HD]
__device__ __half g_Vh[(size_t)B_ * H_ * T_ * HD_];   // [B,H,T,HD] (t-major)
__device__ __half g_Yh[(size_t)M_ * C_];              // attention out [M,C]
__device__ __half g_xh[(size_t)M_ * C_];              // x fp16        [M,K]
__device__ __half g_Wqkvh[(size_t)C_ * NQKV];         // Wqkv fp16     [K,N] native
__device__ __half g_Wprojh[(size_t)C_ * C_];          // Wproj fp16    [K,N] native

// ---------------------------------------------------------------------------
// Helpers
// ---------------------------------------------------------------------------
__device__ __forceinline__ uint32_t smem_to_u32(const void* p) {
    uint32_t a;
    asm("{ .reg .u64 t; cvta.to.shared.u64 t, %1; cvt.u32.u64 %0, t; }"
        : "=r"(a) : "l"(p));
    return a;
}
__device__ __forceinline__ void cp_async16(uint32_t smem_addr, const void* gptr) {
    asm volatile("cp.async.cg.shared.global [%0], [%1], 16;"
                 :: "r"(smem_addr), "l"(gptr) : "memory");
}
#define CP_ASYNC_COMMIT() asm volatile("cp.async.commit_group;" ::: "memory")
#define CP_ASYNC_WAIT_ALL() asm volatile("cp.async.wait_group 0;" ::: "memory")
#define CP_ASYNC_WAIT_1()   asm volatile("cp.async.wait_group 1;" ::: "memory")
#define CP_ASYNC_WAIT_2()   asm volatile("cp.async.wait_group 2;" ::: "memory")

// m16n8k16 fp16 MMA, fp32 accumulate (sm_70+ baseline PTX)
__device__ __forceinline__ void mma_f16(float c[4],
                                        uint32_t a0, uint32_t a1, uint32_t a2, uint32_t a3,
                                        uint32_t b0, uint32_t b1) {
    asm volatile(
        "mma.sync.aligned.m16n8k16.row.col.f32.f16.f16.f32 "
        "{%0,%1,%2,%3}, {%4,%5,%6,%7}, {%8,%9}, {%0,%1,%2,%3};"
        : "+f"(c[0]), "+f"(c[1]), "+f"(c[2]), "+f"(c[3])
        : "r"(a0), "r"(a1), "r"(a2), "r"(a3), "r"(b0), "r"(b1));
}

__device__ __forceinline__ void ldsm_x4(uint32_t& r0, uint32_t& r1,
                                        uint32_t& r2, uint32_t& r3, uint32_t addr) {
    asm volatile("ldmatrix.sync.aligned.m8n8.x4.shared.b16 {%0,%1,%2,%3}, [%4];"
                 : "=r"(r0), "=r"(r1), "=r"(r2), "=r"(r3) : "r"(addr));
}
__device__ __forceinline__ void ldsm_x4_t(uint32_t& r0, uint32_t& r1,
                                          uint32_t& r2, uint32_t& r3, uint32_t addr) {
    asm volatile("ldmatrix.sync.aligned.m8n8.x4.trans.shared.b16 {%0,%1,%2,%3}, [%4];"
                 : "=r"(r0), "=r"(r1), "=r"(r2), "=r"(r3) : "r"(addr));
}

// ---------------------------------------------------------------------------
// Pre-pass kernels: fp32 -> fp16 conversions.
// cvt_xwq (x + W_qkv) on the main stream; cvt_wp (W_proj) forked to a
// second stream so it overlaps the QKV GEMM + attention.
// ---------------------------------------------------------------------------
constexpr size_t NX  = (size_t)M_ * C_;        //  8,388,608
constexpr size_t NWQ = (size_t)C_ * NQKV;      // 12,582,912
constexpr size_t NWP = (size_t)C_ * C_;        //  4,194,304

__global__ void __launch_bounds__(256)
cvt_xwq(const float* __restrict__ x, const float* __restrict__ wqkv) {
    size_t i = ((size_t)blockIdx.x * 256 + threadIdx.x) * 8;
    const float* src;
    __half* dst;
    size_t off;
    if (i < NX) { src = x;    dst = g_xh;    off = i; }
    else        { src = wqkv; dst = g_Wqkvh; off = i - NX; }
    float4 v0 = *(const float4*)(src + off);
    float4 v1 = *(const float4*)(src + off + 4);
    __half2 h[4];
    h[0] = __floats2half2_rn(v0.x, v0.y);
    h[1] = __floats2half2_rn(v0.z, v0.w);
    h[2] = __floats2half2_rn(v1.x, v1.y);
    h[3] = __floats2half2_rn(v1.z, v1.w);
    *(uint4*)(dst + off) = *reinterpret_cast<uint4*>(h);
}

__global__ void __launch_bounds__(256)
cvt_wp(const float* __restrict__ wproj) {
    size_t i = ((size_t)blockIdx.x * 256 + threadIdx.x) * 8;
    float4 v0 = *(const float4*)(wproj + i);
    float4 v1 = *(const float4*)(wproj + i + 4);
    __half2 h[4];
    h[0] = __floats2half2_rn(v0.x, v0.y);
    h[1] = __floats2half2_rn(v0.z, v0.w);
    h[2] = __floats2half2_rn(v1.x, v1.y);
    h[3] = __floats2half2_rn(v1.z, v1.w);
    *(uint4*)(g_Wprojh + i) = *reinterpret_cast<uint4*>(h);
}

// ---------------------------------------------------------------------------
// fp16 tensor GEMM: D[m][n] = sum_k A[m][k] * Bw[k][n], fp32 accumulate.
// 128 threads (4 warps), BM=64, BN=128, BK=32, 4-stage cp.async ring,
// strength-reduced addressing, PEELED TAIL (branch-free hot loop).
// Exact ledger: main loop j in [0, NT-4]: commits issued = 3+j,
// wait_group 2 -> completed >= j+1 (exact). Peeled j=NT-3/NT-2/NT-1 use
// wait 2/1/0 with all NT commits already issued.
// mode 0: out fp32 [m][n] = D + bias[n]
// mode 1: QKV scatter: Q (scaled) / K / V -> [B,H,T,HD] half (coalesced)
// ---------------------------------------------------------------------------
constexpr int AST = 40;    // A tile row stride (halves): 32 + 8 pad
constexpr int BST = 136;   // B tile row stride (halves): 128 + 8 pad
constexpr int A_STAGE = 64 * AST * 2;                  //  5120 B
constexpr int B_STAGE = 32 * BST * 2;                  //  8704 B
constexpr int GEMM_STAGE_BYTES = A_STAGE + B_STAGE;    // 13824
constexpr int GEMM_SMEM_BYTES  = 4 * GEMM_STAGE_BYTES; // 55296
constexpr float QSCALE = 0.08838834764831845f;         // 128^-0.5

__global__ void __launch_bounds__(128, 4)
gemm_h(const __half* __restrict__ A, const __half* __restrict__ Bw,
       const float* __restrict__ bias, float* __restrict__ out,
       int K, int ldB, int mode, int ldo) {
    extern __shared__ __half smh[];
    const uint32_t sb = smem_to_u32(smh);
    const int tid = threadIdx.x;
    const int wid = tid >> 5, lane = tid & 31;
    const int bm = blockIdx.y, bn = blockIdx.x;
    const int wm = (wid >> 1) * 32;      // 0 / 32
    const int wn = (wid & 1) * 64;       // 0 / 64
    const int fr = lane >> 2, tq = lane & 3;

    // A ldmatrix (non-trans) per-lane offset (bytes)
    const uint32_t aoff =
        (uint32_t)(((wm + (lane & 7) + ((lane >> 3) & 1) * 8) * AST
                    + ((lane >> 4) & 1) * 8) * 2);
    // B trans-ldmatrix per-lane offset (halves; rows = k, cols = n)
    const uint32_t btoff =
        (uint32_t)(((lane & 7) + ((lane >> 3) & 1) * 8) * BST
                   + ((lane >> 4) & 1) * 8 + wn);

    float acc[2][8][4];
    #pragma unroll
    for (int mi = 0; mi < 2; mi++)
        #pragma unroll
        for (int ni = 0; ni < 8; ni++)
            #pragma unroll
            for (int q = 0; q < 4; q++) acc[mi][ni][q] = 0.f;

    // ---- precomputed per-thread load offsets (ONCE) ----
    uint32_t aS[2]; const __half* aG[2];
    {
        const __half* gA = A + (size_t)bm * 64 * K;
        const int r0 = tid >> 2, c0 = tid & 3;
        const int r1 = (128 + tid) >> 2;
        aS[0] = (uint32_t)(r0 * (AST * 2) + c0 * 16);
        aG[0] = gA + (size_t)r0 * K + c0 * 8;
        aS[1] = (uint32_t)(r1 * (AST * 2) + c0 * 16);
        aG[1] = gA + (size_t)r1 * K + c0 * 8;
    }
    uint32_t bS[4]; const __half* bG[4];
    {
        const __half* gB = Bw + (size_t)bn * 128;
        const int r = tid >> 4, c = tid & 15;
        #pragma unroll
        for (int i = 0; i < 4; i++) {
            int rr = r + i * 8;
            bS[i] = (uint32_t)(A_STAGE + rr * (BST * 2) + c * 16);
            bG[i] = gB + (size_t)rr * ldB + c * 8;
        }
    }
    const size_t bStride = (size_t)32 * ldB;

    auto load_stage = [&](int s) {
        const uint32_t base = sb + (uint32_t)s * GEMM_STAGE_BYTES;
        #pragma unroll
        for (int i = 0; i < 2; i++) cp_async16(base + aS[i], aG[i]);
        #pragma unroll
        for (int i = 0; i < 4; i++) cp_async16(base + bS[i], bG[i]);
        #pragma unroll
        for (int i = 0; i < 2; i++) aG[i] += 32;
        #pragma unroll
        for (int i = 0; i < 4; i++) bG[i] += bStride;
    };

    auto compute = [&](int st) {
        const uint32_t As_u = sb + (uint32_t)st * GEMM_STAGE_BYTES;
        const uint32_t Bs_u = As_u + A_STAGE;
        #pragma unroll
        for (int ks = 0; ks < 2; ks++) {
            uint32_t a[2][4], bb[4][4];
            #pragma unroll
            for (int mi = 0; mi < 2; mi++)
                ldsm_x4(a[mi][0], a[mi][1], a[mi][2], a[mi][3],
                        As_u + aoff + (uint32_t)((mi * 16 * AST + ks * 16) * 2));
            #pragma unroll
            for (int nj = 0; nj < 4; nj++)
                ldsm_x4_t(bb[nj][0], bb[nj][1], bb[nj][2], bb[nj][3],
                          Bs_u + (uint32_t)((btoff + ks * 16 * BST
                                             + nj * 16) * 2));
            #pragma unroll
            for (int mi = 0; mi < 2; mi++)
                #pragma unroll
                for (int ni = 0; ni < 8; ni++)
                    mma_f16(acc[mi][ni], a[mi][0], a[mi][1], a[mi][2], a[mi][3],
                            bb[ni >> 1][(ni & 1) * 2], bb[ni >> 1][(ni & 1) * 2 + 1]);
        }
    };

    load_stage(0); CP_ASYNC_COMMIT();
    load_stage(1); CP_ASYNC_COMMIT();
    load_stage(2); CP_ASYNC_COMMIT();

    const int NT = K / 32;   // >= 4, multiple of 4
    #pragma unroll 1
    for (int j = 0; j < NT - 3; j++) {
        CP_ASYNC_WAIT_2();          // exact: commits 3+j, need j+1
        __syncthreads();            // compute(j-1) done before overwrite
        load_stage((j + 3) & 3);    // unconditional in this range
        CP_ASYNC_COMMIT();
        compute(j & 3);
    }
    // peeled tail: all NT commits issued; waits exact
    CP_ASYNC_WAIT_2();  __syncthreads(); compute((NT - 3) & 3);
    CP_ASYNC_WAIT_1();  __syncthreads(); compute((NT - 2) & 3);
    CP_ASYNC_WAIT_ALL(); __syncthreads(); compute((NT - 1) & 3);

    const int fc = tq * 2;

    if (mode == 1) {
        const int b  = bm >> 5;               // 32 m-tiles of 64 rows per b
        const int t0 = (bm & 31) * 64;
        const int n0g = bn * 128;
        const int s  = n0g >> 11;             // 0=Q 1=K 2=V
        const int h  = (n0g & 2047) >> 7;
        const float sc = (s == 0) ? QSCALE : 1.f;
        __half* base = ((s == 0) ? g_Qh : (s == 1) ? g_Kh : g_Vh)
                       + (size_t)(b * H_ + h) * T_ * HD_;
        #pragma unroll
        for (int mi = 0; mi < 2; mi++) {
            #pragma unroll
            for (int ni = 0; ni < 8; ni++) {
                int t = t0 + wm + mi * 16 + fr;
                int n = wn + ni * 8 + fc;
                *(__half2*)(base + (size_t)t * HD_ + n) =
                    __floats2half2_rn(acc[mi][ni][0] * sc, acc[mi][ni][1] * sc);
                *(__half2*)(base + (size_t)(t + 8) * HD_ + n) =
                    __floats2half2_rn(acc[mi][ni][2] * sc, acc[mi][ni][3] * sc);
            }
        }
    } else {
        #pragma unroll
        for (int mi = 0; mi < 2; mi++) {
            #pragma unroll
            for (int ni = 0; ni < 8; ni++) {
                int m = bm * 64 + wm + mi * 16 + fr;
                int n = bn * 128 + wn + ni * 8 + fc;
                float b0 = bias[n], b1 = bias[n + 1];
                *(float2*)(out + (size_t)m * ldo + n) =
                    make_float2(acc[mi][ni][0] + b0, acc[mi][ni][1] + b1);
                *(float2*)(out + (size_t)(m + 8) * ldo + n) =
                    make_float2(acc[mi][ni][2] + b0, acc[mi][ni][3] + b1);
            }
        }
    }
}

// ---------------------------------------------------------------------------
// fp16 tensor-core flash attention, causal. Br=128, Bc=64, HD=128, 8 warps.
// (R8/R9 proven version, unchanged)
// ---------------------------------------------------------------------------
constexpr int ASQ = 136;   // Q/K/V row stride, halves (272B: conflict-free)
constexpr int ATTN_SMEM_BYTES = (128 * ASQ + 4 * 64 * ASQ) * 2;   // 104448 B

__global__ void __launch_bounds__(256, 2)
attn_h() {
    extern __shared__ __half smh[];
    const uint32_t qs_b = smem_to_u32(smh);
    const uint32_t kv_b[2][2] = {
        { qs_b + 17408u * 2, qs_b + 26112u * 2 },   // Ks0, Vs0
        { qs_b + 34816u * 2, qs_b + 43520u * 2 }    // Ks1, Vs1
    };

    const int tid = threadIdx.x;
    const int w = tid >> 5, lane = tid & 31;
    const int fr = lane >> 2, tq = lane & 3;
    const int qi = (T_ / 128 - 1) - blockIdx.x;    // heavy blocks first
    const int h = blockIdx.y, b = blockIdx.z;
    const int q0 = qi * 128;

    const __half* Qg = g_Qh + (size_t)(b * H_ + h) * T_ * HD_;
    const __half* Kg = g_Kh + (size_t)(b * H_ + h) * T_ * HD_;
    const __half* Vg = g_Vh + (size_t)(b * H_ + h) * T_ * HD_;

    const uint32_t a_row = (lane & 7) + ((lane >> 3) & 1) * 8;
    const uint32_t a_col8 = ((lane >> 4) & 1) * 8;
    const uint32_t b_row = (lane & 7) + ((lane >> 4) & 1) * 8;
    const uint32_t b_col8 = ((lane >> 3) & 1) * 8;
    const uint32_t q_off = (uint32_t)(((w * 16 + a_row) * ASQ + a_col8) * 2);
    const uint32_t k_off = (uint32_t)((b_row * ASQ + b_col8) * 2);
    const uint32_t v_off = (uint32_t)((a_row * ASQ + a_col8) * 2);

    auto load_kv = [&](int buf, int k0) {
        #pragma unroll
        for (int i = 0; i < 4; i++) {
            int u = i * 256 + tid;
            int r = u >> 4, c = u & 15;
            cp_async16(kv_b[buf][0] + r * (ASQ * 2) + c * 16,
                       Kg + (size_t)(k0 + r) * HD_ + c * 8);
        }
        #pragma unroll
        for (int i = 0; i < 4; i++) {
            int u = i * 256 + tid;
            int r = u >> 4, c = u & 15;
            cp_async16(kv_b[buf][1] + r * (ASQ * 2) + c * 16,
                       Vg + (size_t)(k0 + r) * HD_ + c * 8);
        }
    };

    #pragma unroll
    for (int i = 0; i < 8; i++) {
        int u = i * 256 + tid;
        int r = u >> 4, c = u & 15;
        cp_async16(qs_b + r * (ASQ * 2) + c * 16,
                   Qg + (size_t)(q0 + r) * HD_ + c * 8);
    }
    load_kv(0, 0);
    CP_ASYNC_COMMIT();

    const int qrow0 = q0 + w * 16 + fr;
    const int qrow1 = qrow0 + 8;

    float m0 = -1e30f, m1 = -1e30f, l0 = 0.f, l1 = 0.f;
    float o[16][4];
    #pragma unroll
    for (int nf = 0; nf < 16; nf++)
        #pragma unroll
        for (int q = 0; q < 4; q++) o[nf][q] = 0.f;

    const int nkt = 2 * qi + 2;
    for (int kt = 0; kt < nkt; kt++) {
        const int k0 = kt * 64;
        const uint32_t ks_u = kv_b[kt & 1][0];
        const uint32_t vs_u = kv_b[kt & 1][1];

        CP_ASYNC_WAIT_ALL();
        __syncthreads();
        if (kt + 1 < nkt)
            load_kv((kt + 1) & 1, k0 + 64);
        CP_ASYNC_COMMIT();

        // ---- S = Q K^T ----
        float s[8][4];
        #pragma unroll
        for (int nf = 0; nf < 8; nf++)
            #pragma unroll
            for (int q = 0; q < 4; q++) s[nf][q] = 0.f;

        #pragma unroll
        for (int ks = 0; ks < 8; ks++) {
            uint32_t a0, a1, a2, a3, bb[4][4];
            ldsm_x4(a0, a1, a2, a3, qs_b + q_off + (uint32_t)(ks * 32));
            #pragma unroll
            for (int nj = 0; nj < 4; nj++)
                ldsm_x4(bb[nj][0], bb[nj][1], bb[nj][2], bb[nj][3],
                        ks_u + k_off + (uint32_t)((nj * 16 * ASQ) * 2 + ks * 32));
            #pragma unroll
            for (int nf = 0; nf < 8; nf++)
                mma_f16(s[nf], a0, a1, a2, a3,
                        bb[nf >> 1][(nf & 1) * 2], bb[nf >> 1][(nf & 1) * 2 + 1]);
        }

        // ---- causal mask ----
        if (kt >= 2 * qi) {
            #pragma unroll
            for (int nf = 0; nf < 8; nf++) {
                int col = k0 + nf * 8 + 2 * tq;
                if (col     > qrow0) s[nf][0] = -1e30f;
                if (col + 1 > qrow0) s[nf][1] = -1e30f;
                if (col     > qrow1) s[nf][2] = -1e30f;
                if (col + 1 > qrow1) s[nf][3] = -1e30f;
            }
        }

        // ---- online softmax ----
        float mx0 = -1e30f, mx1 = -1e30f;
        #pragma unroll
        for (int nf = 0; nf < 8; nf++) {
            mx0 = fmaxf(mx0, fmaxf(s[nf][0], s[nf][1]));
            mx1 = fmaxf(mx1, fmaxf(s[nf][2], s[nf][3]));
        }
        mx0 = fmaxf(mx0, __shfl_xor_sync(0xffffffffu, mx0, 1));
        mx0 = fmaxf(mx0, __shfl_xor_sync(0xffffffffu, mx0, 2));
        mx1 = fmaxf(mx1, __shfl_xor_sync(0xffffffffu, mx1, 1));
        mx1 = fmaxf(mx1, __shfl_xor_sync(0xffffffffu, mx1, 2));

        float mn0 = fmaxf(m0, mx0), mn1 = fmaxf(m1, mx1);
        float al0 = __expf(m0 - mn0), al1 = __expf(m1 - mn1);

        uint32_t pa[4][4];
        float ps0 = 0.f, ps1 = 0.f;
        #pragma unroll
        for (int nf = 0; nf < 8; nf++) {
            float p0 = __expf(s[nf][0] - mn0);
            float p1 = __expf(s[nf][1] - mn0);
            float p2 = __expf(s[nf][2] - mn1);
            float p3 = __expf(s[nf][3] - mn1);
            ps0 += p0 + p1; ps1 += p2 + p3;
            const int ks2 = nf >> 1, lo = (nf & 1) * 2;
            __half2 h01 = __floats2half2_rn(p0, p1);
            __half2 h23 = __floats2half2_rn(p2, p3);
            pa[ks2][lo]     = *reinterpret_cast<uint32_t*>(&h01);
            pa[ks2][lo + 1] = *reinterpret_cast<uint32_t*>(&h23);
        }
        ps0 += __shfl_xor_sync(0xffffffffu, ps0, 1);
        ps0 += __shfl_xor_sync(0xffffffffu, ps0, 2);
        ps1 += __shfl_xor_sync(0xffffffffu, ps1, 1);
        ps1 += __shfl_xor_sync(0xffffffffu, ps1, 2);
        l0 = l0 * al0 + ps0; m0 = mn0;
        l1 = l1 * al1 + ps1; m1 = mn1;

        #pragma unroll
        for (int nf = 0; nf < 16; nf++) {
            o[nf][0] *= al0; o[nf][1] *= al0;
            o[nf][2] *= al1; o[nf][3] *= al1;
        }

        // ---- O += P V : 8 d-tiles cover full HD=128 ----
        #pragma unroll
        for (int ks2 = 0; ks2 < 4; ks2++) {
            #pragma unroll
            for (int nj = 0; nj < 8; nj++) {
                uint32_t r0, r1, r2, r3;
                ldsm_x4_t(r0, r1, r2, r3,
                          vs_u + v_off +
                          (uint32_t)((ks2 * 16 * ASQ + nj * 16) * 2));
                mma_f16(o[nj * 2],     pa[ks2][0], pa[ks2][1], pa[ks2][2], pa[ks2][3], r0, r1);
                mma_f16(o[nj * 2 + 1], pa[ks2][0], pa[ks2][1], pa[ks2][2], pa[ks2][3], r2, r3);
            }
        }
    }

    // ---- epilogue ----
    const float inv0 = 1.f / l0, inv1 = 1.f / l1;
    __half* y0 = g_Yh + (size_t)(b * T_ + qrow0) * C_ + h * HD_;
    __half* y1 = g_Yh + (size_t)(b * T_ + qrow1) * C_ + h * HD_;
    #pragma unroll
    for (int nf = 0; nf < 16; nf++) {
        int c = nf * 8 + 2 * tq;
        *(__half2*)(y0 + c) = __floats2half2_rn(o[nf][0] * inv0, o[nf][1] * inv0);
        *(__half2*)(y1 + c) = __floats2half2_rn(o[nf][2] * inv1, o[nf][3] * inv1);
    }
}

// ---------------------------------------------------------------------------
// Launch. Inputs (metadata order): x, mask, W_qkv, W_proj, b_proj
// W_proj conversion forked onto a second stream (overlaps QKV + attention),
// joined via event before the proj GEMM. Standard capturable fork/join.
// ---------------------------------------------------------------------------
extern "C" void kernel_launch(void* const* d_in, const int* in_sizes, int n_in,
                              void* d_out, int out_size) {
    const float* x     = (const float*)d_in[0];
    const float* Wqkv  = (const float*)d_in[2];
    const float* Wproj = (const float*)d_in[3];
    const float* bproj = (const float*)d_in[4];
    float* out = (float*)d_out;

    static cudaStream_t s2 = nullptr;
    static cudaEvent_t e1 = nullptr, e2 = nullptr;
    if (s2 == nullptr) {
        cudaFuncSetAttribute(attn_h,
                             cudaFuncAttributeMaxDynamicSharedMemorySize,
                             ATTN_SMEM_BYTES);
        cudaFuncSetAttribute(gemm_h,
                             cudaFuncAttributeMaxDynamicSharedMemorySize,
                             GEMM_SMEM_BYTES);
        cudaStreamCreateWithFlags(&s2, cudaStreamNonBlocking);
        cudaEventCreateWithFlags(&e1, cudaEventDisableTiming);
        cudaEventCreateWithFlags(&e2, cudaEventDisableTiming);
    }

    __half* xh;  cudaGetSymbolAddress((void**)&xh,  g_xh);
    __half* wq;  cudaGetSymbolAddress((void**)&wq,  g_Wqkvh);
    __half* wp;  cudaGetSymbolAddress((void**)&wp,  g_Wprojh);
    __half* yh;  cudaGetSymbolAddress((void**)&yh,  g_Yh);

    // Fork W_proj conversion onto s2 (runs alongside cvt_xwq + QKV + attn)
    cudaEventRecord(e1, 0);
    cudaStreamWaitEvent(s2, e1, 0);
    cvt_wp<<<(int)(NWP / 2048), 256, 0, s2>>>(Wproj);
    cudaEventRecord(e2, s2);

    // x + W_qkv conversion on the main stream
    cvt_xwq<<<(int)((NX + NWQ) / 2048), 256>>>(x, Wqkv);

    // QKV projection (fp16 tensor cores), B native [K,N]; scatter Q/K/V
    gemm_h<<<dim3(NQKV / 128, M_ / 64), 128, GEMM_SMEM_BYTES>>>(
        xh, wq, nullptr, nullptr, C_, NQKV, 1, 0);

    // Attention (fp16 tensor-core flash, causal)
    attn_h<<<dim3(T_ / 128, H_, B_), 256, ATTN_SMEM_BYTES>>>();

    // Join: W_proj fp16 must be ready before the proj GEMM
    cudaStreamWaitEvent(0, e2, 0);

    // Output projection (fp16 tensor cores) + fp32 bias
    gemm_h<<<dim3(C_ / 128, M_ / 64), 128, GEMM_SMEM_BYTES>>>(
        yh, wp, bproj, out, C_, C_, 0, C_);
}